// round 11
// baseline (speedup 1.0000x reference)
#include <cuda_runtime.h>
#include <math.h>
#include <cstdint>

#define NPATCH 196
#define IPB    2                 // images per block
#define BLOCK  (IPB * 64)        // 2 warps per image

#define FMA_F32X2(d, a, b, c) \
    asm("fma.rn.f32x2 %0, %1, %2, %3;" : "=l"(d) : "l"(a), "l"(b), "l"(c))
#define PACK_F32X2(out, lo, hi) \
    asm("mov.b64 %0, {%1, %2};" : "=l"(out) : "f"(lo), "f"(hi))
#define UNPACK_F32X2(lo, hi, in) \
    asm("mov.b64 {%0, %1}, %2;" : "=f"(lo), "=f"(hi) : "l"(in))

__global__ __launch_bounds__(BLOCK, 7)   // 73-reg cap -> 7 blocks (28 warps)/SM, single wave
void quanv_fused_kernel(const float* __restrict__ x,
                        const float* __restrict__ emb_W,
                        const float* __restrict__ emb_b,
                        const float* __restrict__ q_params,
                        const float* __restrict__ lin_W,
                        const float* __restrict__ lin_b,
                        float* __restrict__ out,
                        int B)
{
    __shared__ float shalf[IPB][2][10];

    const int warp = threadIdx.x >> 5;   // 0..3
    const int lane = threadIdx.x & 31;
    const int img  = warp >> 1;          // image slot in block
    const int h    = warp & 1;           // half id
    const int b    = blockIdx.x * IPB + img;
    const bool valid = (b < B);
    const int bs = valid ? b : 0;        // safe base; stores gated by `valid`

    // ---- uniform circuit constants ----
    const float Kc0 = __cosf(q_params[0]);
    const float Kq1 = q_params[1];
    float s4, c4;
    __sincosf(q_params[4], &s4, &c4);
    const float Ks4 = s4 * __cosf(q_params[2]);
    const float Kc3 = __cosf(q_params[3]);

    const float4 W0 = __ldg((const float4*)(emb_W + 0));
    const float4 W1 = __ldg((const float4*)(emb_W + 4));
    const float4 W2 = __ldg((const float4*)(emb_W + 8));
    const float4 W3 = __ldg((const float4*)(emb_W + 12));
    const float4 eb = __ldg((const float4*)emb_b);

    const float*   xb  = x + bs * 784;
    const double2* lw2 = (const double2*)lin_W;

    // half h owns rounds {h, h+2, h+4} -> p = lane + 32*(h + 2*kk), kk=0..2
    // tail patches 192..195 go to half 1 as round kk=3 (lanes 0..3, clamped addr)
    const int  nk = 3 + h;               // h=0: 3 rounds, h=1: 4 rounds
    const bool tl = (lane < 4);
    const int  pt = 192 + (tl ? lane : 0);

    // ---- phase A: front-batch this half's image loads (MLP up to 8) ----
    float2 tp[4], bt[4];
#pragma unroll
    for (int kk = 0; kk < 4; kk++) {
        if (kk >= nk) break;             // warp-uniform
        const int p  = (kk < 3) ? (lane + 32 * (h + 2 * kk)) : pt;
        const int pr = p / 14, pc = p % 14;
        tp[kk] = *(const float2*)(xb + (2 * pr) * 28 + 2 * pc);
        bt[kk] = *(const float2*)(xb + (2 * pr + 1) * 28 + 2 * pc);
    }

    // ---- phase B+C: features + packed GEMV, 10 packed accumulator chains ----
    unsigned long long acc2[10];
#pragma unroll
    for (int c = 0; c < 10; c++) acc2[c] = 0ull;

#pragma unroll
    for (int kk = 0; kk < 4; kk++) {
        if (kk >= nk) break;             // warp-uniform
        const int p = (kk < 3) ? (lane + 32 * (h + 2 * kk)) : pt;

        const float2 T = tp[kk], Bt = bt[kk];
        const float a0 = fmaf(T.x, W0.x, fmaf(T.y, W0.y, fmaf(Bt.x, W0.z, fmaf(Bt.y, W0.w, eb.x))));
        const float a1 = fmaf(T.x, W1.x, fmaf(T.y, W1.y, fmaf(Bt.x, W1.z, fmaf(Bt.y, W1.w, eb.y))));
        const float a2 = fmaf(T.x, W2.x, fmaf(T.y, W2.y, fmaf(Bt.x, W2.z, fmaf(Bt.y, W2.w, eb.z))));
        const float a3 = fmaf(T.x, W3.x, fmaf(T.y, W3.y, fmaf(Bt.x, W3.z, fmaf(Bt.y, W3.w, eb.w))));

        const float ca0  = __cosf(a0);
        const float ca1q = __cosf(a1 + Kq1);
        float sa2, ca2, sa3, ca3;
        __sincosf(a2, &sa2, &ca2);
        __sincosf(a3, &sa3, &ca3);

        float e0 = Kc0 * ca0;
        float e1 = e0 * ca1q;
        float e2 = e1 * fmaf(c4, ca2, -Ks4 * sa2 * sa3);
        float e3 = ca2 * (Kc3 * ca3);

        if (kk == 3 && !tl) { e0 = 0.f; e1 = 0.f; e2 = 0.f; e3 = 0.f; }

        unsigned long long E01, E23;
        PACK_F32X2(E01, e0, e1);
        PACK_F32X2(E23, e2, e3);

#pragma unroll
        for (int c = 0; c < 10; c++) {
            const double2 wd = __ldg(&lw2[c * NPATCH + p]);
            const unsigned long long wxy = __double_as_longlong(wd.x);
            const unsigned long long wzw = __double_as_longlong(wd.y);
            FMA_F32X2(acc2[c], E23, wzw, acc2[c]);
            FMA_F32X2(acc2[c], E01, wxy, acc2[c]);
        }
    }

    // collapse packed pairs
    float acc[10];
#pragma unroll
    for (int c = 0; c < 10; c++) {
        float lo, hi;
        UNPACK_F32X2(lo, hi, acc2[c]);
        acc[c] = lo + hi;
    }

    // ---- intra-warp xor-butterfly (this half's 10 sums in every lane) ----
#pragma unroll
    for (int off = 16; off > 0; off >>= 1)
#pragma unroll
        for (int c = 0; c < 10; c++)
            acc[c] += __shfl_xor_sync(0xffffffffu, acc[c], off);

    // handoff: predicated selection chain (no dynamic reg indexing)
    {
        float v = acc[0];
#pragma unroll
        for (int c = 1; c < 10; c++) if (lane == c) v = acc[c];
        if (lane < 10) shalf[img][h][lane] = v;
    }
    __syncthreads();

    // ---- half 0 finishes: combine, log_softmax, coalesced store ----
    if (h == 0 && lane < 10 && valid) {
        float lg[10];
#pragma unroll
        for (int c = 0; c < 10; c++)
            lg[c] = shalf[img][0][c] + shalf[img][1][c] + __ldg(&lin_b[c]);

        float mx = lg[0];
#pragma unroll
        for (int c = 1; c < 10; c++) mx = fmaxf(mx, lg[c]);
        float se = 0.f;
#pragma unroll
        for (int c = 0; c < 10; c++) se += __expf(lg[c] - mx);
        const float lse = mx + __logf(se);

        float v = lg[0];
#pragma unroll
        for (int c = 1; c < 10; c++) if (lane == c) v = lg[c];
        out[b * 10 + lane] = v - lse;
    }
}

extern "C" void kernel_launch(void* const* d_in, const int* in_sizes, int n_in,
                              void* d_out, int out_size)
{
    const float* x        = (const float*)d_in[0];
    const float* emb_W    = (const float*)d_in[1];
    const float* emb_b    = (const float*)d_in[2];
    const float* q_params = (const float*)d_in[3];
    const float* lin_W    = (const float*)d_in[4];
    const float* lin_b    = (const float*)d_in[5];
    float* out = (float*)d_out;

    const int B = in_sizes[0] / 784;
    const int grid = (B + IPB - 1) / IPB;
    quanv_fused_kernel<<<grid, BLOCK>>>(x, emb_W, emb_b, q_params, lin_W, lin_b, out, B);
}

// round 12
// speedup vs baseline: 1.0776x; 1.0776x over previous
#include <cuda_runtime.h>
#include <math.h>
#include <cstdint>

#define NPATCH 196
#define IPB    2                 // images per block
#define BLOCK  (IPB * 64)        // 2 warps per image

#define FMA_F32X2(d, a, b, c) \
    asm("fma.rn.f32x2 %0, %1, %2, %3;" : "=l"(d) : "l"(a), "l"(b), "l"(c))
#define PACK_F32X2(out, lo, hi) \
    asm("mov.b64 %0, {%1, %2};" : "=l"(out) : "f"(lo), "f"(hi))
#define UNPACK_F32X2(lo, hi, in) \
    asm("mov.b64 {%0, %1}, %2;" : "=f"(lo), "=f"(hi) : "l"(in))

struct __align__(16) FeatPack { unsigned long long e01, e23; };

__global__ __launch_bounds__(BLOCK, 7)   // regs<=73 -> 7 blocks (28 warps)/SM
void quanv_fused_kernel(const float* __restrict__ x,
                        const float* __restrict__ emb_W,
                        const float* __restrict__ emb_b,
                        const float* __restrict__ q_params,
                        const float* __restrict__ lin_W,
                        const float* __restrict__ lin_b,
                        float* __restrict__ out,
                        int B)
{
    __shared__ FeatPack sE[IPB][7][32];   // packed features per image/round/lane
    __shared__ float    slog[IPB][10];

    const int warp = threadIdx.x >> 5;    // 0..3
    const int lane = threadIdx.x & 31;
    const int img  = warp >> 1;
    const int h    = warp & 1;            // half id
    const int b    = blockIdx.x * IPB + img;
    const bool valid = (b < B);
    const int bs = valid ? b : 0;

    // ---- uniform circuit constants ----
    const float Kc0 = __cosf(q_params[0]);
    const float Kq1 = q_params[1];
    float s4, c4;
    __sincosf(q_params[4], &s4, &c4);
    const float Ks4 = s4 * __cosf(q_params[2]);
    const float Kc3 = __cosf(q_params[3]);

    const float4 W0 = __ldg((const float4*)(emb_W + 0));
    const float4 W1 = __ldg((const float4*)(emb_W + 4));
    const float4 W2 = __ldg((const float4*)(emb_W + 8));
    const float4 W3 = __ldg((const float4*)(emb_W + 12));
    const float4 eb = __ldg((const float4*)emb_b);

    const float*   xb  = x + bs * 784;
    const double2* lw2 = (const double2*)lin_W;

    // ---- phase A/B: compute this half's feature rounds, store packed to smem ----
    // h=0 owns rounds {0,1,2,6(tail)}; h=1 owns rounds {3,4,5}
    const int nr = 4 - h;                 // h=0: 4 rounds, h=1: 3 rounds
    const bool tl = (lane < 4);
#pragma unroll
    for (int r = 0; r < 4; r++) {
        if (r >= nr) break;               // warp-uniform
        const int k = (h == 0) ? ((r < 3) ? r : 6) : (3 + r);
        const bool tail = (k == 6);
        const int p = tail ? (192 + (tl ? lane : 0)) : (lane + 32 * k);

        const int pr = p / 14, pc = p % 14;
        const float2 T  = *(const float2*)(xb + (2 * pr) * 28 + 2 * pc);
        const float2 Bt = *(const float2*)(xb + (2 * pr + 1) * 28 + 2 * pc);

        const float a0 = fmaf(T.x, W0.x, fmaf(T.y, W0.y, fmaf(Bt.x, W0.z, fmaf(Bt.y, W0.w, eb.x))));
        const float a1 = fmaf(T.x, W1.x, fmaf(T.y, W1.y, fmaf(Bt.x, W1.z, fmaf(Bt.y, W1.w, eb.y))));
        const float a2 = fmaf(T.x, W2.x, fmaf(T.y, W2.y, fmaf(Bt.x, W2.z, fmaf(Bt.y, W2.w, eb.z))));
        const float a3 = fmaf(T.x, W3.x, fmaf(T.y, W3.y, fmaf(Bt.x, W3.z, fmaf(Bt.y, W3.w, eb.w))));

        const float ca0  = __cosf(a0);
        const float ca1q = __cosf(a1 + Kq1);
        float sa2, ca2, sa3, ca3;
        __sincosf(a2, &sa2, &ca2);
        __sincosf(a3, &sa3, &ca3);

        float e0 = Kc0 * ca0;
        float e1 = e0 * ca1q;
        float e2 = e1 * fmaf(c4, ca2, -Ks4 * sa2 * sa3);
        float e3 = ca2 * (Kc3 * ca3);

        if (tail && !tl) { e0 = 0.f; e1 = 0.f; e2 = 0.f; e3 = 0.f; }

        FeatPack fp;
        PACK_F32X2(fp.e01, e0, e1);
        PACK_F32X2(fp.e23, e2, e3);
        sE[img][k][lane] = fp;            // STS.128
    }
    __syncthreads();

    // ---- phase C: GEMV over ALL patches for this half's 5 channels ----
    const int c0 = 5 * h;
    unsigned long long acc2[5];
#pragma unroll
    for (int c = 0; c < 5; c++) acc2[c] = 0ull;

#pragma unroll
    for (int k = 0; k < 7; k++) {
        const int p = (k < 6) ? (lane + 32 * k) : (192 + (lane & 3)); // safe addr; feats 0 if invalid
        const FeatPack fp = sE[img][k][lane];                          // LDS.128
#pragma unroll
        for (int c = 0; c < 5; c++) {
            const double2 wd = __ldg(&lw2[(c0 + c) * NPATCH + p]);
            const unsigned long long wxy = __double_as_longlong(wd.x);
            const unsigned long long wzw = __double_as_longlong(wd.y);
            FMA_F32X2(acc2[c], fp.e23, wzw, acc2[c]);
            FMA_F32X2(acc2[c], fp.e01, wxy, acc2[c]);
        }
    }

    float acc[5];
#pragma unroll
    for (int c = 0; c < 5; c++) {
        float lo, hi;
        UNPACK_F32X2(lo, hi, acc2[c]);
        acc[c] = lo + hi;
    }

    // ---- 5-channel xor-butterfly ----
#pragma unroll
    for (int off = 16; off > 0; off >>= 1)
#pragma unroll
        for (int c = 0; c < 5; c++)
            acc[c] += __shfl_xor_sync(0xffffffffu, acc[c], off);

    // handoff: lanes 0..4 write this half's logits (predicated selection, no dyn idx)
    {
        float v = acc[0];
#pragma unroll
        for (int c = 1; c < 5; c++) if (lane == c) v = acc[c];
        if (lane < 5) slog[img][c0 + lane] = v;
    }
    __syncthreads();

    // ---- h=0 finishes: bias + log_softmax + coalesced store ----
    if (h == 0 && lane < 10 && valid) {
        float lg[10];
#pragma unroll
        for (int c = 0; c < 10; c++) lg[c] = slog[img][c] + __ldg(&lin_b[c]);

        float mx = lg[0];
#pragma unroll
        for (int c = 1; c < 10; c++) mx = fmaxf(mx, lg[c]);
        float se = 0.f;
#pragma unroll
        for (int c = 0; c < 10; c++) se += __expf(lg[c] - mx);
        const float lse = mx + __logf(se);

        float v = lg[0];
#pragma unroll
        for (int c = 1; c < 10; c++) if (lane == c) v = lg[c];
        out[b * 10 + lane] = v - lse;
    }
}

extern "C" void kernel_launch(void* const* d_in, const int* in_sizes, int n_in,
                              void* d_out, int out_size)
{
    const float* x        = (const float*)d_in[0];
    const float* emb_W    = (const float*)d_in[1];
    const float* emb_b    = (const float*)d_in[2];
    const float* q_params = (const float*)d_in[3];
    const float* lin_W    = (const float*)d_in[4];
    const float* lin_b    = (const float*)d_in[5];
    float* out = (float*)d_out;

    const int B = in_sizes[0] / 784;
    const int grid = (B + IPB - 1) / IPB;
    quanv_fused_kernel<<<grid, BLOCK>>>(x, emb_W, emb_b, q_params, lin_W, lin_b, out, B);
}

// round 13
// speedup vs baseline: 1.2804x; 1.1882x over previous
#include <cuda_runtime.h>
#include <math.h>
#include <cstdint>

#define NPATCH 196
#define BLOCK  128   // 4 warps = 2 pairs; each pair handles 2 images -> 4 images/block

#define FMA_F32X2(d, a, b, c) \
    asm("fma.rn.f32x2 %0, %1, %2, %3;" : "=l"(d) : "l"(a), "l"(b), "l"(c))
#define PACK_F32X2(out, lo, hi) \
    asm("mov.b64 %0, {%1, %2};" : "=l"(out) : "f"(lo), "f"(hi))
#define UNPACK_F32X2(lo, hi, in) \
    asm("mov.b64 {%0, %1}, %2;" : "=f"(lo), "=f"(hi) : "l"(in))

__global__ __launch_bounds__(BLOCK, 4)   // reg cap 128; 512 blocks -> 3.5/SM, single wave
void quanv_fused_kernel(const float* __restrict__ x,
                        const float* __restrict__ emb_W,
                        const float* __restrict__ emb_b,
                        const float* __restrict__ q_params,
                        const float* __restrict__ lin_W,
                        const float* __restrict__ lin_b,
                        float* __restrict__ out,
                        int B)
{
    __shared__ float spart[2][2][2][10];   // [pair][h(writer)][img][chan]

    const int warp = threadIdx.x >> 5;     // 0..3
    const int lane = threadIdx.x & 31;
    const int pair = warp >> 1;
    const int h    = warp & 1;             // round-half id
    const int bA   = blockIdx.x * 4 + pair * 2;   // image A; image B = bA+1
    const bool vA  = (bA < B), vB = (bA + 1 < B);
    const int sA   = vA ? bA : 0, sB = vB ? (bA + 1) : 0;

    // ---- uniform circuit constants ----
    const float Kc0 = __cosf(q_params[0]);
    const float Kq1 = q_params[1];
    float s4, c4;
    __sincosf(q_params[4], &s4, &c4);
    const float Ks4 = s4 * __cosf(q_params[2]);
    const float Kc3 = __cosf(q_params[3]);

    const float4 W0 = __ldg((const float4*)(emb_W + 0));
    const float4 W1 = __ldg((const float4*)(emb_W + 4));
    const float4 W2 = __ldg((const float4*)(emb_W + 8));
    const float4 W3 = __ldg((const float4*)(emb_W + 12));
    const float4 eb = __ldg((const float4*)emb_b);

    const float*   xA  = x + sA * 784;
    const float*   xB  = x + sB * 784;
    const double2* lw2 = (const double2*)lin_W;

    // warp h owns rounds: h=0 -> {0,1,2,6(tail)} ; h=1 -> {3,4,5}
    const int nr = 4 - h;
    const bool tl = (lane < 4);

    // ---- phase A: front-batch x loads for BOTH images (MLP up to 16) ----
    float2 tpA[4], btA[4], tpB[4], btB[4];
#pragma unroll
    for (int r = 0; r < 4; r++) {
        if (r >= nr) break;                               // warp-uniform
        const int k = (h == 0) ? ((r < 3) ? r : 6) : (3 + r);
        const int p = (k < 6) ? (lane + 32 * k) : (192 + (tl ? lane : 0));
        const int pr = p / 14, pc = p % 14;
        const int o0 = (2 * pr) * 28 + 2 * pc, o1 = o0 + 28;
        tpA[r] = *(const float2*)(xA + o0);
        btA[r] = *(const float2*)(xA + o1);
        tpB[r] = *(const float2*)(xB + o0);
        btB[r] = *(const float2*)(xB + o1);
    }

    // ---- phase B: features for both images ----
    unsigned long long E01A[4], E23A[4], E01B[4], E23B[4];
#pragma unroll
    for (int r = 0; r < 4; r++) {
        if (r >= nr) break;                               // warp-uniform
        const int k = (h == 0) ? ((r < 3) ? r : 6) : (3 + r);
        const bool tail = (k == 6);
#pragma unroll
        for (int im = 0; im < 2; im++) {
            const float2 T  = im ? tpB[r] : tpA[r];
            const float2 Bt = im ? btB[r] : btA[r];
            const float a0 = fmaf(T.x, W0.x, fmaf(T.y, W0.y, fmaf(Bt.x, W0.z, fmaf(Bt.y, W0.w, eb.x))));
            const float a1 = fmaf(T.x, W1.x, fmaf(T.y, W1.y, fmaf(Bt.x, W1.z, fmaf(Bt.y, W1.w, eb.y))));
            const float a2 = fmaf(T.x, W2.x, fmaf(T.y, W2.y, fmaf(Bt.x, W2.z, fmaf(Bt.y, W2.w, eb.z))));
            const float a3 = fmaf(T.x, W3.x, fmaf(T.y, W3.y, fmaf(Bt.x, W3.z, fmaf(Bt.y, W3.w, eb.w))));

            const float ca0  = __cosf(a0);
            const float ca1q = __cosf(a1 + Kq1);
            float sa2, ca2, sa3, ca3;
            __sincosf(a2, &sa2, &ca2);
            __sincosf(a3, &sa3, &ca3);

            float e0 = Kc0 * ca0;
            float e1 = e0 * ca1q;
            float e2 = e1 * fmaf(c4, ca2, -Ks4 * sa2 * sa3);
            float e3 = ca2 * (Kc3 * ca3);
            if (tail && !tl) { e0 = 0.f; e1 = 0.f; e2 = 0.f; e3 = 0.f; }

            if (im) { PACK_F32X2(E01B[r], e0, e1); PACK_F32X2(E23B[r], e2, e3); }
            else    { PACK_F32X2(E01A[r], e0, e1); PACK_F32X2(E23A[r], e2, e3); }
        }
    }

    // ---- phase C: GEMV over this half's rounds; each weight load feeds 2 images ----
    float aA[10], aB[10];
#pragma unroll
    for (int c = 0; c < 10; c++) {
        unsigned long long accA = 0ull, accB = 0ull;
#pragma unroll
        for (int r = 0; r < 4; r++) {
            if (r >= nr) break;                           // warp-uniform
            const int k = (h == 0) ? ((r < 3) ? r : 6) : (3 + r);
            const int p = (k < 6) ? (lane + 32 * k) : (192 + (tl ? lane : 0));
            const double2 wd = __ldg(&lw2[c * NPATCH + p]);
            const unsigned long long wxy = __double_as_longlong(wd.x);
            const unsigned long long wzw = __double_as_longlong(wd.y);
            FMA_F32X2(accA, E23A[r], wzw, accA);
            FMA_F32X2(accA, E01A[r], wxy, accA);
            FMA_F32X2(accB, E23B[r], wzw, accB);
            FMA_F32X2(accB, E01B[r], wxy, accB);
        }
        float lo, hi;
        UNPACK_F32X2(lo, hi, accA); aA[c] = lo + hi;
        UNPACK_F32X2(lo, hi, accB); aB[c] = lo + hi;
    }

    // ---- xor-butterfly both images' partials ----
#pragma unroll
    for (int off = 16; off > 0; off >>= 1)
#pragma unroll
        for (int c = 0; c < 10; c++) {
            aA[c] += __shfl_xor_sync(0xffffffffu, aA[c], off);
            aB[c] += __shfl_xor_sync(0xffffffffu, aB[c], off);
        }

    // handoff (predicated selection, no dynamic reg indexing)
    {
        float vAv = aA[0], vBv = aB[0];
#pragma unroll
        for (int c = 1; c < 10; c++) if (lane == c) { vAv = aA[c]; vBv = aB[c]; }
        if (lane < 10) {
            spart[pair][h][0][lane] = vAv;
            spart[pair][h][1][lane] = vBv;
        }
    }
    __syncthreads();

    // ---- finalize: warp h finishes image h of its pair (balanced) ----
    const int  bO = bA + h;
    const bool vO = (h == 0) ? vA : vB;
    if (lane < 10 && vO) {
        float lg[10];
#pragma unroll
        for (int c = 0; c < 10; c++)
            lg[c] = spart[pair][0][h][c] + spart[pair][1][h][c] + __ldg(&lin_b[c]);

        float mx = lg[0];
#pragma unroll
        for (int c = 1; c < 10; c++) mx = fmaxf(mx, lg[c]);
        float se = 0.f;
#pragma unroll
        for (int c = 0; c < 10; c++) se += __expf(lg[c] - mx);
        const float lse = mx + __logf(se);

        float v = lg[0];
#pragma unroll
        for (int c = 1; c < 10; c++) if (lane == c) v = lg[c];
        out[bO * 10 + lane] = v - lse;
    }
}

extern "C" void kernel_launch(void* const* d_in, const int* in_sizes, int n_in,
                              void* d_out, int out_size)
{
    const float* x        = (const float*)d_in[0];
    const float* emb_W    = (const float*)d_in[1];
    const float* emb_b    = (const float*)d_in[2];
    const float* q_params = (const float*)d_in[3];
    const float* lin_W    = (const float*)d_in[4];
    const float* lin_b    = (const float*)d_in[5];
    float* out = (float*)d_out;

    const int B = in_sizes[0] / 784;
    const int grid = (B + 3) / 4;
    quanv_fused_kernel<<<grid, BLOCK>>>(x, emb_W, emb_b, q_params, lin_W, lin_b, out, B);
}